// round 16
// baseline (speedup 1.0000x reference)
#include <cuda_runtime.h>

#define H   8
#define LQ  384
#define LK  384
#define DQ  32
#define DV  32
#define DC  64
#define BS  2

#define K2 2.8853900817779268f   // 2*log2(e)
#define FLT_BIG 3.4e38f
#define ONE2 0x3F8000003F800000ULL

// scratch: g_A[b,h,q,e] = exp(2*(q@W1_top + b1));  g_Ct[b,h,e,k] = exp(2*(k@W1_bot))
__device__ float g_A [BS * H * LQ * DC];
__device__ float g_Ct[BS * H * DC * LK];

__device__ __forceinline__ float ex2a(float x) {
    float r; asm("ex2.approx.f32 %0, %1;" : "=f"(r) : "f"(x)); return r;
}
__device__ __forceinline__ float rcpa(float x) {
    float r; asm("rcp.approx.f32 %0, %1;" : "=f"(r) : "f"(x)); return r;
}
__device__ __forceinline__ unsigned long long fma2(unsigned long long a,
                                                   unsigned long long b,
                                                   unsigned long long c) {
    unsigned long long r;
    asm("fma.rn.f32x2 %0, %1, %2, %3;" : "=l"(r) : "l"(a), "l"(b), "l"(c));
    return r;
}
__device__ __forceinline__ unsigned long long mul2(unsigned long long a,
                                                   unsigned long long b) {
    unsigned long long r;
    asm("mul.rn.f32x2 %0, %1, %2;" : "=l"(r) : "l"(a), "l"(b));
    return r;
}
__device__ __forceinline__ unsigned long long pack2(float lo, float hi) {
    unsigned long long r;
    asm("mov.b64 %0, {%1, %2};" : "=l"(r) : "f"(lo), "f"(hi));
    return r;
}
__device__ __forceinline__ void unpack2(unsigned long long v, float& lo, float& hi) {
    asm("mov.b64 {%0, %1}, %2;" : "=f"(lo), "=f"(hi) : "l"(v));
}

// 4-way rcp combining for one packed k-pair (u64 of 2 floats):
// acc += (w0/d0 + w1/d1 + w2/d3 + w3/d3) with ONE rcp per float lane.
__device__ __forceinline__ void equad(
    unsigned long long tAx, unsigned long long tAy,
    unsigned long long tBx, unsigned long long tBy,
    unsigned long long wAx, unsigned long long wAy,
    unsigned long long wBx, unsigned long long wBy,
    unsigned long long c0, unsigned long long c1,
    unsigned long long c2, unsigned long long c3,
    unsigned long long& acc)
{
    unsigned long long d0 = fma2(tAx, c0, ONE2);
    unsigned long long d1 = fma2(tAy, c1, ONE2);
    unsigned long long d2 = fma2(tBx, c2, ONE2);
    unsigned long long d3 = fma2(tBy, c3, ONE2);
    unsigned long long n01 = fma2(wAx, d1, mul2(wAy, d0));
    unsigned long long n23 = fma2(wBx, d3, mul2(wBy, d2));
    unsigned long long d01 = mul2(d0, d1);
    unsigned long long d23 = mul2(d2, d3);
    unsigned long long n   = fma2(n01, d23, mul2(n23, d01));
    unsigned long long dd  = mul2(d01, d23);
    float f0, f1;
    unpack2(dd, f0, f1);
    unsigned long long rr = pack2(rcpa(f0), rcpa(f1));
    acc = fma2(n, rr, acc);
}

// Tiled precompute (measured good): 96 blocks, all GMEM coalesced.
__global__ void __launch_bounds__(256)
precompute(const float* __restrict__ q, const float* __restrict__ kin,
           const float* __restrict__ w1, const float* __restrict__ b1) {
    __shared__ float sX[128][DQ + 1];
    __shared__ float sW[DQ][DC];
    __shared__ float sB[DC];

    int tid  = threadIdx.x;
    int bid  = blockIdx.x;
    int side = bid >= (BS * H * 3) ? 1 : 0;
    int loc  = bid - side * (BS * H * 3);
    int bh   = loc / 3;
    int tile = loc % 3;
    int h    = bh & (H - 1);
    int b    = bh >> 3;
    int rbase = tile * 128;

    const float* src = side ? kin : q;
    for (int i = tid; i < 128 * DQ; i += 256) {
        int r = i >> 5, d = i & 31;
        sX[r][d] = src[((size_t)(b * 384 + rbase + r)) * (H * DQ) + h * DQ + d];
    }
    for (int i = tid; i < DQ * DC; i += 256) {
        int d = i >> 6, e = i & 63;
        sW[d][e] = w1[h * DC * DC + (side * DQ + d) * DC + e];
    }
    if (tid < DC) sB[tid] = side ? 0.f : b1[h * DC + tid];
    __syncthreads();

    if (side == 0) {
        for (int o = tid; o < 128 * DC; o += 256) {
            int r = o >> 6, e = o & 63;
            float acc = sB[e];
#pragma unroll
            for (int d = 0; d < DQ; d++) acc = fmaf(sX[r][d], sW[d][e], acc);
            g_A[((size_t)(bh * LQ + rbase + r)) * DC + e] = ex2a(K2 * acc);
        }
    } else {
        for (int o = tid; o < DC * 128; o += 256) {
            int e = o >> 7, kk = o & 127;
            float acc = 0.f;
#pragma unroll
            for (int d = 0; d < DQ; d++) acc = fmaf(sX[kk][d], sW[d][e], acc);
            g_Ct[((size_t)(bh * DC + e)) * LK + rbase + kk] = ex2a(K2 * acc);
        }
    }
}

// BATCH-BALANCED blocks: block = (h, 4-row group); quad 0 -> b=0, quad 1 -> b=1.
// Block = 192 threads = 6 warps = 2 quads x 3 k-chunks; pass-1 packed f32x2,
// ONE rcp per 4 e-terms (4-way partial-fraction combining).
__global__ void __launch_bounds__(192)
attn_kernel(const float* __restrict__ w2, const float* __restrict__ v,
            const int* __restrict__ qlen, const int* __restrict__ klen,
            float* __restrict__ out, float* __restrict__ att) {
    __shared__ unsigned long long sTA2[8][DC];
    __shared__ unsigned long long sW22[DC];
    __shared__ float sP  [8][LK];
    __shared__ float sMn [8][3];
    __shared__ float sSum[8][3];
    __shared__ float sOut[8][3][DV];

    int tid  = threadIdx.x;
    int warp = tid >> 5;
    int lane = tid & 31;
    int rp    = (warp >= 3) ? 1 : 0;
    int chunk = warp - rp * 3;
    int r0    = rp * 4;

    int bid = blockIdx.x;                // grid = H * 96
    int h   = bid / 96;
    int grp = bid % 96;
    int qbase = grp * 4;

    for (int i = tid; i < 8 * DC; i += 192) {
        int lr = i >> 6, e = i & 63;
        int bq = lr >> 2, rr = lr & 3;
        float va = g_A[((size_t)((bq * H + h) * LQ + qbase + rr)) * DC + e];
        sTA2[lr][e] = pack2(va, va);
    }
    if (tid < DC) {
        float wv = w2[h * DC + tid];
        sW22[tid] = pack2(wv, wv);
    }
    __syncthreads();

    const int b     = rp;
    const int bh    = b * H + h;
    const int kl    = klen[b];
    const int kbase = chunk << 7;
    const float* ct = g_Ct + (size_t)bh * DC * LK;

    // ---- pass 1: 4 rows x 4 k per lane; 4 e per rcp ----
    float mn[4]  = {FLT_BIG, FLT_BIG, FLT_BIG, FLT_BIG};
    float sum[4] = {0.f, 0.f, 0.f, 0.f};
    float acc[4][4];
    if (kbase < kl) {
        const float* cpf = ct + kbase + lane * 4;
        unsigned long long accp[4][2];
#pragma unroll
        for (int r = 0; r < 4; r++) { accp[r][0] = 0ULL; accp[r][1] = 0ULL; }
#pragma unroll 2
        for (int eq = 0; eq < DC / 4; eq++) {
            ulonglong2 wA = *(const ulonglong2*)&sW22[4 * eq];
            ulonglong2 wB = *(const ulonglong2*)&sW22[4 * eq + 2];
            ulonglong2 c0 = *(const ulonglong2*)(cpf + (4 * eq)     * LK);
            ulonglong2 c1 = *(const ulonglong2*)(cpf + (4 * eq + 1) * LK);
            ulonglong2 c2 = *(const ulonglong2*)(cpf + (4 * eq + 2) * LK);
            ulonglong2 c3 = *(const ulonglong2*)(cpf + (4 * eq + 3) * LK);
#pragma unroll
            for (int r = 0; r < 4; r++) {
                ulonglong2 tA = *(const ulonglong2*)&sTA2[r0 + r][4 * eq];
                ulonglong2 tB = *(const ulonglong2*)&sTA2[r0 + r][4 * eq + 2];
                equad(tA.x, tA.y, tB.x, tB.y, wA.x, wA.y, wB.x, wB.y,
                      c0.x, c1.x, c2.x, c3.x, accp[r][0]);
                equad(tA.x, tA.y, tB.x, tB.y, wA.x, wA.y, wB.x, wB.y,
                      c0.y, c1.y, c2.y, c3.y, accp[r][1]);
            }
        }
#pragma unroll
        for (int r = 0; r < 4; r++) {
            unpack2(accp[r][0], acc[r][0], acc[r][1]);
            unpack2(accp[r][1], acc[r][2], acc[r][3]);
        }
#pragma unroll
        for (int r = 0; r < 4; r++)
#pragma unroll
            for (int j = 0; j < 4; j++)
                if (kbase + lane * 4 + j < kl) mn[r] = fminf(mn[r], acc[r][j]);
#pragma unroll
        for (int o = 16; o; o >>= 1)
#pragma unroll
            for (int r = 0; r < 4; r++)
                mn[r] = fminf(mn[r], __shfl_xor_sync(0xffffffffu, mn[r], o));
#pragma unroll
        for (int r = 0; r < 4; r++) {
            int kk = kbase + lane * 4;
            float p0 = (kk     < kl) ? ex2a(K2 * (mn[r] - acc[r][0])) : 0.f;
            float p1 = (kk + 1 < kl) ? ex2a(K2 * (mn[r] - acc[r][1])) : 0.f;
            float p2 = (kk + 2 < kl) ? ex2a(K2 * (mn[r] - acc[r][2])) : 0.f;
            float p3 = (kk + 3 < kl) ? ex2a(K2 * (mn[r] - acc[r][3])) : 0.f;
            sum[r] = (p0 + p1) + (p2 + p3);
            *(float4*)&sP[r0 + r][kbase + lane * 4] = make_float4(p0, p1, p2, p3);
        }
#pragma unroll
        for (int o = 16; o; o >>= 1)
#pragma unroll
            for (int r = 0; r < 4; r++)
                sum[r] += __shfl_xor_sync(0xffffffffu, sum[r], o);
    } else {
#pragma unroll
        for (int r = 0; r < 4; r++)
            *(float4*)&sP[r0 + r][kbase + lane * 4] = make_float4(0.f, 0.f, 0.f, 0.f);
    }
    if (lane == 0) {
#pragma unroll
        for (int r = 0; r < 4; r++) { sMn[r0 + r][chunk] = mn[r]; sSum[r0 + r][chunk] = sum[r]; }
    }
    __syncthreads();

    // ---- combine chunks exactly: rinv_c = scale_c / total ----
    float rinvc[4];
#pragma unroll
    for (int r = 0; r < 4; r++) {
        float m0 = sMn[r0 + r][0], m1 = sMn[r0 + r][1], m2 = sMn[r0 + r][2];
        float mg = fminf(fminf(m0, m1), m2);
        float s0 = (m0 < FLT_BIG) ? ex2a(K2 * (mg - m0)) : 0.f;
        float s1 = (m1 < FLT_BIG) ? ex2a(K2 * (mg - m1)) : 0.f;
        float s2 = (m2 < FLT_BIG) ? ex2a(K2 * (mg - m2)) : 0.f;
        float total = fmaf(sSum[r0 + r][0], s0,
                      fmaf(sSum[r0 + r][1], s1, sSum[r0 + r][2] * s2));
        float sc = (chunk == 0) ? s0 : (chunk == 1) ? s1 : s2;
        rinvc[r] = sc / total;
    }

    // ---- att rows ----
#pragma unroll
    for (int r = 0; r < 4; r++) {
        float4 pv = *(const float4*)&sP[r0 + r][kbase + lane * 4];
        *(float4*)(att + ((size_t)(bh * LQ + qbase + r)) * LK + kbase + lane * 4) =
            make_float4(pv.x * rinvc[r], pv.y * rinvc[r], pv.z * rinvc[r], pv.w * rinvc[r]);
    }

    // ---- AV: lane -> (kg, dv4); each v float4 shared by 4 rows ----
    int kg  = lane >> 3;
    int dv4 = (lane & 7) << 2;
    float4 o[4];
#pragma unroll
    for (int r = 0; r < 4; r++) o[r] = make_float4(0.f, 0.f, 0.f, 0.f);
    int kcap = kl - kbase; if (kcap > 128) kcap = 128;
    const float* vb = v + ((size_t)(b * LK + kbase + kg)) * (H * DV) + h * DV + dv4;
    for (int kk = kg; kk < kcap; kk += 4, vb += 4 * (H * DV)) {
        float4 vv = *(const float4*)vb;
#pragma unroll
        for (int r = 0; r < 4; r++) {
            float pr = sP[r0 + r][kbase + kk];
            o[r].x = fmaf(pr, vv.x, o[r].x);
            o[r].y = fmaf(pr, vv.y, o[r].y);
            o[r].z = fmaf(pr, vv.z, o[r].z);
            o[r].w = fmaf(pr, vv.w, o[r].w);
        }
    }
#pragma unroll
    for (int off = 8; off <= 16; off <<= 1) {
#pragma unroll
        for (int r = 0; r < 4; r++) {
            o[r].x += __shfl_xor_sync(0xffffffffu, o[r].x, off);
            o[r].y += __shfl_xor_sync(0xffffffffu, o[r].y, off);
            o[r].z += __shfl_xor_sync(0xffffffffu, o[r].z, off);
            o[r].w += __shfl_xor_sync(0xffffffffu, o[r].w, off);
        }
    }
    if (kg == 0) {
#pragma unroll
        for (int r = 0; r < 4; r++)
            *(float4*)&sOut[r0 + r][chunk][dv4] =
                make_float4(o[r].x * rinvc[r], o[r].y * rinvc[r],
                            o[r].z * rinvc[r], o[r].w * rinvc[r]);
    }
    __syncthreads();

    // ---- finalize ----
    if (chunk == 0) {
        const int ql = qlen[b];
#pragma unroll
        for (int r = 0; r < 4; r++) {
            int lr = r0 + r;
            int qi = qbase + r;
            float oo = (sOut[lr][0][lane] + sOut[lr][1][lane]) + sOut[lr][2][lane];
            if (qi >= ql) oo = 0.f;
            out[((size_t)(b * LQ + qi)) * (H * DV) + h * DV + lane] = oo;
        }
    }
}

extern "C" void kernel_launch(void* const* d_in, const int* in_sizes, int n_in,
                              void* d_out, int out_size) {
    const float* q    = (const float*)d_in[0];
    const float* k    = (const float*)d_in[1];
    const float* v    = (const float*)d_in[2];
    const int*   qlen = (const int*)  d_in[3];
    const int*   klen = (const int*)  d_in[4];
    const float* w1   = (const float*)d_in[5];
    const float* b1   = (const float*)d_in[6];
    const float* w2   = (const float*)d_in[7];

    float* out = (float*)d_out;
    float* att = out + (size_t)BS * LQ * H * DV;

    precompute<<<2 * BS * H * 3, 256>>>(q, k, w1, b1);
    attn_kernel<<<H * 96, 192>>>(w2, v, qlen, klen, out, att);
}

// round 17
// speedup vs baseline: 1.0360x; 1.0360x over previous
#include <cuda_runtime.h>

#define H   8
#define LQ  384
#define LK  384
#define DQ  32
#define DV  32
#define DC  64
#define BS  2

#define K2 2.8853900817779268f   // 2*log2(e)
#define FLT_BIG 3.4e38f
#define ONE2 0x3F8000003F800000ULL

// scratch: g_A[b,h,q,e] = exp(2*(q@W1_top + b1));  g_Ct[b,h,e,k] = exp(2*(k@W1_bot))
__device__ float g_A [BS * H * LQ * DC];
__device__ float g_Ct[BS * H * DC * LK];

__device__ __forceinline__ float ex2a(float x) {
    float r; asm("ex2.approx.f32 %0, %1;" : "=f"(r) : "f"(x)); return r;
}
__device__ __forceinline__ float rcpa(float x) {
    float r; asm("rcp.approx.f32 %0, %1;" : "=f"(r) : "f"(x)); return r;
}
__device__ __forceinline__ unsigned long long fma2(unsigned long long a,
                                                   unsigned long long b,
                                                   unsigned long long c) {
    unsigned long long r;
    asm("fma.rn.f32x2 %0, %1, %2, %3;" : "=l"(r) : "l"(a), "l"(b), "l"(c));
    return r;
}
__device__ __forceinline__ unsigned long long mul2(unsigned long long a,
                                                   unsigned long long b) {
    unsigned long long r;
    asm("mul.rn.f32x2 %0, %1, %2;" : "=l"(r) : "l"(a), "l"(b));
    return r;
}
__device__ __forceinline__ unsigned long long add2(unsigned long long a,
                                                   unsigned long long b) {
    unsigned long long r;
    asm("add.rn.f32x2 %0, %1, %2;" : "=l"(r) : "l"(a), "l"(b));
    return r;
}
__device__ __forceinline__ unsigned long long pack2(float lo, float hi) {
    unsigned long long r;
    asm("mov.b64 %0, {%1, %2};" : "=l"(r) : "f"(lo), "f"(hi));
    return r;
}
__device__ __forceinline__ void unpack2(unsigned long long v, float& lo, float& hi) {
    asm("mov.b64 {%0, %1}, %2;" : "=f"(lo), "=f"(hi) : "l"(v));
}

// 8-way rcp combining: acc += sum_{i=0..7} w_i/d_i with ONE rcp per fp32 lane.
// c[i*cstride] selects this k-pair's column out of interleaved ulonglong2 loads.
__device__ __forceinline__ void equad8(
    const unsigned long long* t, const unsigned long long* w,
    const unsigned long long* c, int cstride, unsigned long long& acc)
{
    unsigned long long d[8];
#pragma unroll
    for (int i = 0; i < 8; i++) d[i] = fma2(t[i], c[i * cstride], ONE2);
    unsigned long long n01 = fma2(w[0], d[1], mul2(w[1], d[0]));
    unsigned long long n23 = fma2(w[2], d[3], mul2(w[3], d[2]));
    unsigned long long n45 = fma2(w[4], d[5], mul2(w[5], d[4]));
    unsigned long long n67 = fma2(w[6], d[7], mul2(w[7], d[6]));
    unsigned long long d01 = mul2(d[0], d[1]);
    unsigned long long d23 = mul2(d[2], d[3]);
    unsigned long long d45 = mul2(d[4], d[5]);
    unsigned long long d67 = mul2(d[6], d[7]);
    unsigned long long n0123 = fma2(n01, d23, mul2(n23, d01));
    unsigned long long n4567 = fma2(n45, d67, mul2(n67, d45));
    unsigned long long d0123 = mul2(d01, d23);
    unsigned long long d4567 = mul2(d45, d67);
    unsigned long long n  = fma2(n0123, d4567, mul2(n4567, d0123));
    unsigned long long dd = mul2(d0123, d4567);
    float f0, f1;
    unpack2(dd, f0, f1);
    unsigned long long rr = pack2(rcpa(f0), rcpa(f1));
    acc = fma2(n, rr, acc);
}

// Tiled precompute (measured good): 96 blocks, all GMEM coalesced.
__global__ void __launch_bounds__(256)
precompute(const float* __restrict__ q, const float* __restrict__ kin,
           const float* __restrict__ w1, const float* __restrict__ b1) {
    __shared__ float sX[128][DQ + 1];
    __shared__ float sW[DQ][DC];
    __shared__ float sB[DC];

    int tid  = threadIdx.x;
    int bid  = blockIdx.x;
    int side = bid >= (BS * H * 3) ? 1 : 0;
    int loc  = bid - side * (BS * H * 3);
    int bh   = loc / 3;
    int tile = loc % 3;
    int h    = bh & (H - 1);
    int b    = bh >> 3;
    int rbase = tile * 128;

    const float* src = side ? kin : q;
    for (int i = tid; i < 128 * DQ; i += 256) {
        int r = i >> 5, d = i & 31;
        sX[r][d] = src[((size_t)(b * 384 + rbase + r)) * (H * DQ) + h * DQ + d];
    }
    for (int i = tid; i < DQ * DC; i += 256) {
        int d = i >> 6, e = i & 63;
        sW[d][e] = w1[h * DC * DC + (side * DQ + d) * DC + e];
    }
    if (tid < DC) sB[tid] = side ? 0.f : b1[h * DC + tid];
    __syncthreads();

    if (side == 0) {
        for (int o = tid; o < 128 * DC; o += 256) {
            int r = o >> 6, e = o & 63;
            float acc = sB[e];
#pragma unroll
            for (int d = 0; d < DQ; d++) acc = fmaf(sX[r][d], sW[d][e], acc);
            g_A[((size_t)(bh * LQ + rbase + r)) * DC + e] = ex2a(K2 * acc);
        }
    } else {
        for (int o = tid; o < DC * 128; o += 256) {
            int e = o >> 7, kk = o & 127;
            float acc = 0.f;
#pragma unroll
            for (int d = 0; d < DQ; d++) acc = fmaf(sX[kk][d], sW[d][e], acc);
            g_Ct[((size_t)(bh * DC + e)) * LK + rbase + kk] = ex2a(K2 * acc);
        }
    }
}

// BATCH-BALANCED blocks: block = (h, 4-row group); quad 0 -> b=0, quad 1 -> b=1.
// Block = 192 threads = 6 warps = 2 quads x 3 k-chunks; pass-1 packed f32x2,
// ONE rcp per 8 e-terms; AV pass also packed f32x2.
__global__ void __launch_bounds__(192)
attn_kernel(const float* __restrict__ w2, const float* __restrict__ v,
            const int* __restrict__ qlen, const int* __restrict__ klen,
            float* __restrict__ out, float* __restrict__ att) {
    __shared__ unsigned long long sTA2[8][DC];
    __shared__ unsigned long long sW22[DC];
    __shared__ float sP  [8][LK];
    __shared__ float sMn [8][3];
    __shared__ float sSum[8][3];
    __shared__ float sOut[8][3][DV];

    int tid  = threadIdx.x;
    int warp = tid >> 5;
    int lane = tid & 31;
    int rp    = (warp >= 3) ? 1 : 0;
    int chunk = warp - rp * 3;
    int r0    = rp * 4;

    int bid = blockIdx.x;                // grid = H * 96
    int h   = bid / 96;
    int grp = bid % 96;
    int qbase = grp * 4;

    for (int i = tid; i < 8 * DC; i += 192) {
        int lr = i >> 6, e = i & 63;
        int bq = lr >> 2, rr = lr & 3;
        float va = g_A[((size_t)((bq * H + h) * LQ + qbase + rr)) * DC + e];
        sTA2[lr][e] = pack2(va, va);
    }
    if (tid < DC) {
        float wv = w2[h * DC + tid];
        sW22[tid] = pack2(wv, wv);
    }
    __syncthreads();

    const int b     = rp;
    const int bh    = b * H + h;
    const int kl    = klen[b];
    const int kbase = chunk << 7;
    const float* ct = g_Ct + (size_t)bh * DC * LK;

    // ---- pass 1: 4 rows x 4 k per lane; 8 e per rcp ----
    float mn[4]  = {FLT_BIG, FLT_BIG, FLT_BIG, FLT_BIG};
    float sum[4] = {0.f, 0.f, 0.f, 0.f};
    float acc[4][4];
    if (kbase < kl) {
        const float* cpf = ct + kbase + lane * 4;
        unsigned long long accp[4][2];
#pragma unroll
        for (int r = 0; r < 4; r++) { accp[r][0] = 0ULL; accp[r][1] = 0ULL; }
#pragma unroll
        for (int eq = 0; eq < DC / 8; eq++) {
            unsigned long long w[8];
            unsigned long long cc[16];   // [e][kpair] interleaved: cc[2i]=kp0, cc[2i+1]=kp1
#pragma unroll
            for (int i = 0; i < 4; i++)
                *(ulonglong2*)&w[2 * i] = *(const ulonglong2*)&sW22[8 * eq + 2 * i];
#pragma unroll
            for (int i = 0; i < 8; i++)
                *(ulonglong2*)&cc[2 * i] = *(const ulonglong2*)(cpf + (8 * eq + i) * LK);
#pragma unroll
            for (int r = 0; r < 4; r++) {
                unsigned long long t[8];
#pragma unroll
                for (int i = 0; i < 4; i++)
                    *(ulonglong2*)&t[2 * i] = *(const ulonglong2*)&sTA2[r0 + r][8 * eq + 2 * i];
                equad8(t, w, &cc[0], 2, accp[r][0]);
                equad8(t, w, &cc[1], 2, accp[r][1]);
            }
        }
#pragma unroll
        for (int r = 0; r < 4; r++) {
            unpack2(accp[r][0], acc[r][0], acc[r][1]);
            unpack2(accp[r][1], acc[r][2], acc[r][3]);
        }
#pragma unroll
        for (int r = 0; r < 4; r++)
#pragma unroll
            for (int j = 0; j < 4; j++)
                if (kbase + lane * 4 + j < kl) mn[r] = fminf(mn[r], acc[r][j]);
#pragma unroll
        for (int o = 16; o; o >>= 1)
#pragma unroll
            for (int r = 0; r < 4; r++)
                mn[r] = fminf(mn[r], __shfl_xor_sync(0xffffffffu, mn[r], o));
#pragma unroll
        for (int r = 0; r < 4; r++) {
            int kk = kbase + lane * 4;
            float p0 = (kk     < kl) ? ex2a(K2 * (mn[r] - acc[r][0])) : 0.f;
            float p1 = (kk + 1 < kl) ? ex2a(K2 * (mn[r] - acc[r][1])) : 0.f;
            float p2 = (kk + 2 < kl) ? ex2a(K2 * (mn[r] - acc[r][2])) : 0.f;
            float p3 = (kk + 3 < kl) ? ex2a(K2 * (mn[r] - acc[r][3])) : 0.f;
            sum[r] = (p0 + p1) + (p2 + p3);
            *(float4*)&sP[r0 + r][kbase + lane * 4] = make_float4(p0, p1, p2, p3);
        }
#pragma unroll
        for (int o = 16; o; o >>= 1)
#pragma unroll
            for (int r = 0; r < 4; r++)
                sum[r] += __shfl_xor_sync(0xffffffffu, sum[r], o);
    } else {
#pragma unroll
        for (int r = 0; r < 4; r++)
            *(float4*)&sP[r0 + r][kbase + lane * 4] = make_float4(0.f, 0.f, 0.f, 0.f);
    }
    if (lane == 0) {
#pragma unroll
        for (int r = 0; r < 4; r++) { sMn[r0 + r][chunk] = mn[r]; sSum[r0 + r][chunk] = sum[r]; }
    }
    __syncthreads();

    // ---- combine chunks exactly: rinv_c = scale_c / total ----
    float rinvc[4];
#pragma unroll
    for (int r = 0; r < 4; r++) {
        float m0 = sMn[r0 + r][0], m1 = sMn[r0 + r][1], m2 = sMn[r0 + r][2];
        float mg = fminf(fminf(m0, m1), m2);
        float s0 = (m0 < FLT_BIG) ? ex2a(K2 * (mg - m0)) : 0.f;
        float s1 = (m1 < FLT_BIG) ? ex2a(K2 * (mg - m1)) : 0.f;
        float s2 = (m2 < FLT_BIG) ? ex2a(K2 * (mg - m2)) : 0.f;
        float total = fmaf(sSum[r0 + r][0], s0,
                      fmaf(sSum[r0 + r][1], s1, sSum[r0 + r][2] * s2));
        float sc = (chunk == 0) ? s0 : (chunk == 1) ? s1 : s2;
        rinvc[r] = sc / total;
    }

    // ---- att rows ----
#pragma unroll
    for (int r = 0; r < 4; r++) {
        float4 pv = *(const float4*)&sP[r0 + r][kbase + lane * 4];
        *(float4*)(att + ((size_t)(bh * LQ + qbase + r)) * LK + kbase + lane * 4) =
            make_float4(pv.x * rinvc[r], pv.y * rinvc[r], pv.z * rinvc[r], pv.w * rinvc[r]);
    }

    // ---- AV (packed f32x2): lane -> (kg, dv4); each v u64-pair shared by 4 rows ----
    int kg  = lane >> 3;
    int dv4 = (lane & 7) << 2;
    unsigned long long o2[4][2];
#pragma unroll
    for (int r = 0; r < 4; r++) { o2[r][0] = 0ULL; o2[r][1] = 0ULL; }
    int kcap = kl - kbase; if (kcap > 128) kcap = 128;
    const float* vb = v + ((size_t)(b * LK + kbase + kg)) * (H * DV) + h * DV + dv4;
    for (int kk = kg; kk < kcap; kk += 4, vb += 4 * (H * DV)) {
        ulonglong2 vv = *(const ulonglong2*)vb;
#pragma unroll
        for (int r = 0; r < 4; r++) {
            float pr = sP[r0 + r][kbase + kk];
            unsigned long long pp = pack2(pr, pr);
            o2[r][0] = fma2(pp, vv.x, o2[r][0]);
            o2[r][1] = fma2(pp, vv.y, o2[r][1]);
        }
    }
#pragma unroll
    for (int off = 8; off <= 16; off <<= 1) {
#pragma unroll
        for (int r = 0; r < 4; r++) {
            o2[r][0] = add2(o2[r][0], __shfl_xor_sync(0xffffffffu, o2[r][0], off));
            o2[r][1] = add2(o2[r][1], __shfl_xor_sync(0xffffffffu, o2[r][1], off));
        }
    }
    if (kg == 0) {
#pragma unroll
        for (int r = 0; r < 4; r++) {
            float x0, x1, x2, x3;
            unpack2(o2[r][0], x0, x1);
            unpack2(o2[r][1], x2, x3);
            *(float4*)&sOut[r0 + r][chunk][dv4] =
                make_float4(x0 * rinvc[r], x1 * rinvc[r], x2 * rinvc[r], x3 * rinvc[r]);
        }
    }
    __syncthreads();

    // ---- finalize ----
    if (chunk == 0) {
        const int ql = qlen[b];
#pragma unroll
        for (int r = 0; r < 4; r++) {
            int lr = r0 + r;
            int qi = qbase + r;
            float oo = (sOut[lr][0][lane] + sOut[lr][1][lane]) + sOut[lr][2][lane];
            if (qi >= ql) oo = 0.f;
            out[((size_t)(b * LQ + qi)) * (H * DV) + h * DV + lane] = oo;
        }
    }
}

extern "C" void kernel_launch(void* const* d_in, const int* in_sizes, int n_in,
                              void* d_out, int out_size) {
    const float* q    = (const float*)d_in[0];
    const float* k    = (const float*)d_in[1];
    const float* v    = (const float*)d_in[2];
    const int*   qlen = (const int*)  d_in[3];
    const int*   klen = (const int*)  d_in[4];
    const float* w1   = (const float*)d_in[5];
    const float* b1   = (const float*)d_in[6];
    const float* w2   = (const float*)d_in[7];

    float* out = (float*)d_out;
    float* att = out + (size_t)BS * LQ * H * DV;

    precompute<<<2 * BS * H * 3, 256>>>(q, k, w1, b1);
    attn_kernel<<<H * 96, 192>>>(w2, v, qlen, klen, out, att);
}